// round 6
// baseline (speedup 1.0000x reference)
#include <cuda_runtime.h>
#include <cuda_bf16.h>
#include <cstdint>

#define M_NODES 50000
#define M_PAD   50048          // 391 * 128
#define K_NBR   32
#define DCH     256

__device__ float         g_h[M_NODES * DCH];
__device__ __nv_bfloat16 g_xhi[M_PAD * DCH];
__device__ __nv_bfloat16 g_xlo[M_PAD * DCH];
__device__ __nv_bfloat16 g_whi[DCH * DCH];
__device__ __nv_bfloat16 g_wlo[DCH * DCH];

#define XBLOCKS (M_PAD * DCH / 4 / 256)      // 12512
#define WBLOCKS (DCH * DCH / 4 / 256)        // 64

// ===================== split fp32 -> (hi, lo) bf16 ==========================
__global__ void __launch_bounds__(256) convert_xw(const float* __restrict__ x,
                                                  const float* __restrict__ w) {
    if (blockIdx.x < XBLOCKS) {
        size_t i4 = (size_t)blockIdx.x * 256 + threadIdx.x;
        float4 f = make_float4(0.f, 0.f, 0.f, 0.f);
        if (i4 * 4 < (size_t)M_NODES * DCH)
            f = *reinterpret_cast<const float4*>(x + i4 * 4);
        __nv_bfloat162 h01 = __floats2bfloat162_rn(f.x, f.y);
        __nv_bfloat162 h23 = __floats2bfloat162_rn(f.z, f.w);
        __nv_bfloat162 l01 = __floats2bfloat162_rn(f.x - __bfloat162float(h01.x),
                                                   f.y - __bfloat162float(h01.y));
        __nv_bfloat162 l23 = __floats2bfloat162_rn(f.z - __bfloat162float(h23.x),
                                                   f.w - __bfloat162float(h23.y));
        reinterpret_cast<uint2*>(g_xhi)[i4] =
            make_uint2(*reinterpret_cast<uint32_t*>(&h01), *reinterpret_cast<uint32_t*>(&h23));
        reinterpret_cast<uint2*>(g_xlo)[i4] =
            make_uint2(*reinterpret_cast<uint32_t*>(&l01), *reinterpret_cast<uint32_t*>(&l23));
    } else {
        size_t i4 = (size_t)(blockIdx.x - XBLOCKS) * 256 + threadIdx.x;
        float4 f = *reinterpret_cast<const float4*>(w + i4 * 4);
        __nv_bfloat162 h01 = __floats2bfloat162_rn(f.x, f.y);
        __nv_bfloat162 h23 = __floats2bfloat162_rn(f.z, f.w);
        __nv_bfloat162 l01 = __floats2bfloat162_rn(f.x - __bfloat162float(h01.x),
                                                   f.y - __bfloat162float(h01.y));
        __nv_bfloat162 l23 = __floats2bfloat162_rn(f.z - __bfloat162float(h23.x),
                                                   f.w - __bfloat162float(h23.y));
        reinterpret_cast<uint2*>(g_whi)[i4] =
            make_uint2(*reinterpret_cast<uint32_t*>(&h01), *reinterpret_cast<uint32_t*>(&h23));
        reinterpret_cast<uint2*>(g_wlo)[i4] =
            make_uint2(*reinterpret_cast<uint32_t*>(&l01), *reinterpret_cast<uint32_t*>(&l23));
    }
}

// ===================== mma.sync bf16 split GEMM, cp.async 3-stage ===========
// h = x_hi*W_hi (kt 0-7) + x_hi*W_lo (8-15) + x_lo*W_hi (16-23), BK=32.
// Block 128x128, 8 warps (4m x 2n), warp tile 32x64.
#define AS_LD   40                 // bf16 per smem row (32 data + 8 pad) = 80B
#define STAGE_B (128 * AS_LD * 2)  // 10240 B per stage per operand
#define NSTAGE  3
#define GEMM_SMEM (NSTAGE * STAGE_B * 2)   // 61440

__device__ __forceinline__ uint32_t smem_u32(const void* p) {
    uint32_t a;
    asm("{ .reg .u64 t; cvta.to.shared.u64 t, %1; cvt.u32.u64 %0, t; }" : "=r"(a) : "l"(p));
    return a;
}
__device__ __forceinline__ void cp16(uint32_t s, const void* g) {
    asm volatile("cp.async.cg.shared.global [%0], [%1], 16;" :: "r"(s), "l"(g));
}
__device__ __forceinline__ void ldsm_x4(uint32_t* r, uint32_t addr) {
    asm volatile("ldmatrix.sync.aligned.m8n8.x4.shared.b16 {%0,%1,%2,%3}, [%4];"
                 : "=r"(r[0]), "=r"(r[1]), "=r"(r[2]), "=r"(r[3]) : "r"(addr));
}
__device__ __forceinline__ void ldsm_x2(uint32_t* r, uint32_t addr) {
    asm volatile("ldmatrix.sync.aligned.m8n8.x2.shared.b16 {%0,%1}, [%2];"
                 : "=r"(r[0]), "=r"(r[1]) : "r"(addr));
}
__device__ __forceinline__ void mma_bf16(float* d, const uint32_t* a, const uint32_t* b) {
    asm volatile(
        "mma.sync.aligned.m16n8k16.row.col.f32.bf16.bf16.f32 "
        "{%0,%1,%2,%3}, {%4,%5,%6,%7}, {%8,%9}, {%0,%1,%2,%3};"
        : "+f"(d[0]), "+f"(d[1]), "+f"(d[2]), "+f"(d[3])
        : "r"(a[0]), "r"(a[1]), "r"(a[2]), "r"(a[3]), "r"(b[0]), "r"(b[1]));
}

__global__ void __launch_bounds__(256) gemm_mma() {
    extern __shared__ char smem[];
    const uint32_t sA0 = smem_u32(smem);                       // 3 A stages
    const uint32_t sB0 = sA0 + NSTAGE * STAGE_B;               // 3 B stages

    const int tid  = threadIdx.x;
    const int bm   = blockIdx.x * 128;
    const int bn   = blockIdx.y * 128;
    const int warp = tid >> 5, lane = tid & 31;
    const int mw   = warp >> 1, nw = warp & 1;

    float acc[2][8][4];
#pragma unroll
    for (int mt = 0; mt < 2; mt++)
#pragma unroll
        for (int nt = 0; nt < 8; nt++)
#pragma unroll
            for (int q = 0; q < 4; q++) acc[mt][nt][q] = 0.0f;

    auto issue = [&](int kt) {
        const int stage = kt % NSTAGE;
        const __nv_bfloat16* asrc = (kt < 16) ? g_xhi : g_xlo;
        const __nv_bfloat16* bsrc = (kt >= 8 && kt < 16) ? g_wlo : g_whi;
        const int kcol = (kt & 7) * 32;
#pragma unroll
        for (int l = 0; l < 2; l++) {
            int c = tid + l * 256, r = c >> 2, j = c & 3;   // 512 16B chunks each
            cp16(sA0 + stage * STAGE_B + r * 80 + j * 16,
                 asrc + (size_t)(bm + r) * DCH + kcol + j * 8);
            cp16(sB0 + stage * STAGE_B + r * 80 + j * 16,
                 bsrc + (size_t)(bn + r) * DCH + kcol + j * 8);
        }
        asm volatile("cp.async.commit_group;" ::: "memory");
    };

    auto compute = [&](int stage) {
        const uint32_t as_b = sA0 + stage * STAGE_B;
        const uint32_t bs_b = sB0 + stage * STAGE_B;
#pragma unroll
        for (int ks = 0; ks < 2; ks++) {
            const int k0 = ks * 16;
            uint32_t afrag[2][4];
#pragma unroll
            for (int mt = 0; mt < 2; mt++)
                ldsm_x4(afrag[mt], as_b + 2u * ((mw * 32 + mt * 16 + (lane & 15)) * AS_LD +
                                                (lane >> 4) * 8 + k0));
            uint32_t bfrag[8][2];
#pragma unroll
            for (int nt = 0; nt < 8; nt++)
                ldsm_x2(bfrag[nt], bs_b + 2u * ((nw * 64 + nt * 8 + (lane & 7)) * AS_LD +
                                                ((lane >> 3) & 1) * 8 + k0));
#pragma unroll
            for (int mt = 0; mt < 2; mt++)
#pragma unroll
                for (int nt = 0; nt < 8; nt++)
                    mma_bf16(acc[mt][nt], afrag[mt], bfrag[nt]);
        }
    };

    issue(0);
    issue(1);

#pragma unroll 1
    for (int kt = 0; kt < 24; kt++) {
        if (kt < 23)
            asm volatile("cp.async.wait_group 1;" ::: "memory");
        else
            asm volatile("cp.async.wait_group 0;" ::: "memory");
        __syncthreads();
        if (kt + 2 < 24) issue(kt + 2);
        compute(kt % NSTAGE);
    }

    // epilogue: acc -> g_h (fp32)
#pragma unroll
    for (int mt = 0; mt < 2; mt++) {
        const int m0 = bm + mw * 32 + mt * 16 + (lane >> 2);
#pragma unroll
        for (int nt = 0; nt < 8; nt++) {
            const int n = bn + nw * 64 + nt * 8 + (lane & 3) * 2;
            if (m0 < M_NODES)
                *reinterpret_cast<float2*>(&g_h[(size_t)m0 * DCH + n]) =
                    make_float2(acc[mt][nt][0], acc[mt][nt][1]);
            if (m0 + 8 < M_NODES)
                *reinterpret_cast<float2*>(&g_h[(size_t)(m0 + 8) * DCH + n]) =
                    make_float2(acc[mt][nt][2], acc[mt][nt][3]);
        }
    }
}

// ===================== gather + selection network ============================
#define CE(a, b) { float _mn = fminf(v[a], v[b]); \
                   float _mx = fmaxf(v[a], v[b]); \
                   v[a] = _mn; v[b] = _mx; }

#define OEMS16(o) \
    CE(o+0,o+1)  CE(o+2,o+3)   CE(o+4,o+5)   CE(o+6,o+7) \
    CE(o+8,o+9)  CE(o+10,o+11) CE(o+12,o+13) CE(o+14,o+15) \
    CE(o+0,o+2)  CE(o+1,o+3)   CE(o+4,o+6)   CE(o+5,o+7) \
    CE(o+8,o+10) CE(o+9,o+11)  CE(o+12,o+14) CE(o+13,o+15) \
    CE(o+1,o+2)  CE(o+5,o+6)   CE(o+9,o+10)  CE(o+13,o+14) \
    CE(o+0,o+4)  CE(o+1,o+5)   CE(o+2,o+6)   CE(o+3,o+7) \
    CE(o+8,o+12) CE(o+9,o+13)  CE(o+10,o+14) CE(o+11,o+15) \
    CE(o+2,o+4)  CE(o+3,o+5)   CE(o+10,o+12) CE(o+11,o+13) \
    CE(o+1,o+2)  CE(o+3,o+4)   CE(o+5,o+6) \
    CE(o+9,o+10) CE(o+11,o+12) CE(o+13,o+14) \
    CE(o+0,o+8)  CE(o+1,o+9)   CE(o+2,o+10)  CE(o+3,o+11) \
    CE(o+4,o+12) CE(o+5,o+13)  CE(o+6,o+14)  CE(o+7,o+15) \
    CE(o+4,o+8)  CE(o+5,o+9)   CE(o+6,o+10)  CE(o+7,o+11) \
    CE(o+2,o+4)  CE(o+3,o+5)   CE(o+6,o+8) \
    CE(o+7,o+9)  CE(o+10,o+12) CE(o+11,o+13) \
    CE(o+1,o+2)  CE(o+3,o+4)   CE(o+5,o+6)   CE(o+7,o+8) \
    CE(o+9,o+10) CE(o+11,o+12) CE(o+13,o+14)

__global__ void __launch_bounds__(256, 6) gather_trim(
    const void* __restrict__ nbrs_raw,
    float* __restrict__ out)
{
    __shared__ int sn[K_NBR];

    const int node = blockIdx.x;
    const int tid  = threadIdx.x;

    if (tid < K_NBR) {
        const int* w = reinterpret_cast<const int*>(nbrs_raw);
        unsigned m = __ballot_sync(0xffffffffu, w[2 * tid + 1] == 0);
        bool is64 = (m == 0xffffffffu);
        long long idx = is64
            ? reinterpret_cast<const long long*>(nbrs_raw)[(size_t)node * K_NBR + tid]
            : (long long)reinterpret_cast<const int*>(nbrs_raw)[(size_t)node * K_NBR + tid];
        sn[tid] = (int)idx * DCH;
    }
    __syncthreads();

    float v[K_NBR];
#pragma unroll
    for (int k = 0; k < K_NBR; k++)
        v[k] = __ldg(&g_h[sn[k] + tid]);

    OEMS16(0)
    OEMS16(16)

#pragma unroll
    for (int i = 0; i < 16; i++) {
        float a = v[i], b = v[31 - i];
        v[i]      = fminf(a, b);
        v[31 - i] = fmaxf(a, b);
    }
#pragma unroll
    for (int j = 8; j >= 2; j >>= 1)
#pragma unroll
        for (int i = 0; i < j; i++)
            v[i] = fmaxf(v[i], v[i + j]);
#pragma unroll
    for (int j = 8; j >= 2; j >>= 1)
#pragma unroll
        for (int i = 0; i < j; i++)
            v[16 + i] = fminf(v[16 + i], v[16 + i + j]);

    out[(size_t)node * DCH + tid] = (v[0] + v[1] + v[16] + v[17]) * 0.25f;
}

// ===================== launch ===============================================
extern "C" void kernel_launch(void* const* d_in, const int* in_sizes, int n_in,
                              void* d_out, int out_size)
{
    const float* x    = nullptr;
    const void*  nbrs = nullptr;
    const float* W    = nullptr;

    for (int i = 0; i < n_in; i++) {
        if      (in_sizes[i] == M_NODES * DCH)   x    = (const float*)d_in[i];
        else if (in_sizes[i] == M_NODES * K_NBR) nbrs = d_in[i];
        else if (in_sizes[i] == DCH * DCH)       W    = (const float*)d_in[i];
    }
    if (!x)    x    = (const float*)d_in[0];
    if (!nbrs) nbrs = d_in[1];
    if (!W)    W    = (const float*)d_in[2];

    cudaFuncSetAttribute(gemm_mma, cudaFuncAttributeMaxDynamicSharedMemorySize, GEMM_SMEM);

    convert_xw<<<XBLOCKS + WBLOCKS, 256>>>(x, W);

    dim3 ggrid(M_PAD / 128, 2);
    gemm_mma<<<ggrid, 256, GEMM_SMEM>>>();

    gather_trim<<<M_NODES, 256>>>(nbrs, (float*)d_out);
}

// round 7
// speedup vs baseline: 1.1204x; 1.1204x over previous
#include <cuda_runtime.h>
#include <cuda_bf16.h>
#include <cstdint>

#define M_NODES 50000
#define K_NBR   32
#define DCH     256

__device__ float         g_h[M_NODES * DCH];
__device__ __nv_bfloat16 g_whi[DCH * DCH];
__device__ __nv_bfloat16 g_wlo[DCH * DCH];

// ===================== W split (tiny) ========================================
__global__ void __launch_bounds__(256) convert_w(const float* __restrict__ w) {
    size_t i4 = (size_t)blockIdx.x * 256 + threadIdx.x;
    if (i4 * 4 >= (size_t)DCH * DCH) return;
    float4 f = *reinterpret_cast<const float4*>(w + i4 * 4);
    __nv_bfloat162 h01 = __floats2bfloat162_rn(f.x, f.y);
    __nv_bfloat162 h23 = __floats2bfloat162_rn(f.z, f.w);
    __nv_bfloat162 l01 = __floats2bfloat162_rn(f.x - __bfloat162float(h01.x),
                                               f.y - __bfloat162float(h01.y));
    __nv_bfloat162 l23 = __floats2bfloat162_rn(f.z - __bfloat162float(h23.x),
                                               f.w - __bfloat162float(h23.y));
    reinterpret_cast<uint2*>(g_whi)[i4] =
        make_uint2(*reinterpret_cast<uint32_t*>(&h01), *reinterpret_cast<uint32_t*>(&h23));
    reinterpret_cast<uint2*>(g_wlo)[i4] =
        make_uint2(*reinterpret_cast<uint32_t*>(&l01), *reinterpret_cast<uint32_t*>(&l23));
}

// ===================== mma.sync bf16 split GEMM (R5 form, proven 90us) =======
#define AS_LD 40   // halves per smem row (32 data + 8 pad) -> 80B stride

__device__ __forceinline__ uint32_t smem_u32(const void* p) {
    uint32_t a;
    asm("{ .reg .u64 t; cvta.to.shared.u64 t, %1; cvt.u32.u64 %0, t; }" : "=r"(a) : "l"(p));
    return a;
}
__device__ __forceinline__ void ldsm_x4(uint32_t* r, uint32_t addr) {
    asm volatile("ldmatrix.sync.aligned.m8n8.x4.shared.b16 {%0,%1,%2,%3}, [%4];"
                 : "=r"(r[0]), "=r"(r[1]), "=r"(r[2]), "=r"(r[3]) : "r"(addr));
}
__device__ __forceinline__ void ldsm_x2(uint32_t* r, uint32_t addr) {
    asm volatile("ldmatrix.sync.aligned.m8n8.x2.shared.b16 {%0,%1}, [%2];"
                 : "=r"(r[0]), "=r"(r[1]) : "r"(addr));
}
__device__ __forceinline__ void mma_bf16(float* d, const uint32_t* a, const uint32_t* b) {
    asm volatile(
        "mma.sync.aligned.m16n8k16.row.col.f32.bf16.bf16.f32 "
        "{%0,%1,%2,%3}, {%4,%5,%6,%7}, {%8,%9}, {%0,%1,%2,%3};"
        : "+f"(d[0]), "+f"(d[1]), "+f"(d[2]), "+f"(d[3])
        : "r"(a[0]), "r"(a[1]), "r"(a[2]), "r"(a[3]), "r"(b[0]), "r"(b[1]));
}

__global__ void __launch_bounds__(256) gemm_mma(const float* __restrict__ x) {
    __shared__ __align__(16) __nv_bfloat16 As[2][128 * AS_LD];
    __shared__ __align__(16) __nv_bfloat16 Bs[2][128 * AS_LD];

    const int tid  = threadIdx.x;
    const int bm   = blockIdx.x * 128;
    const int bn   = blockIdx.y * 128;
    const int warp = tid >> 5, lane = tid & 31;
    const int mw   = warp >> 1, nw = warp & 1;

    float acc[2][8][4];
#pragma unroll
    for (int mt = 0; mt < 2; mt++)
#pragma unroll
        for (int nt = 0; nt < 8; nt++)
#pragma unroll
            for (int q = 0; q < 4; q++) acc[mt][nt][q] = 0.0f;

    float4 ar[4];
    uint2  br[4];

    auto load_g = [&](int kt) {
        const int seg = kt >> 3;                 // 0: hi*Whi  1: hi*Wlo  2: lo*Whi
        const int kk  = (kt & 7) * 32;
        const __nv_bfloat16* wsrc = (seg == 1) ? g_wlo : g_whi;
#pragma unroll
        for (int l = 0; l < 4; l++) {
            int t = tid + l * 256, r = t >> 3, j = t & 7;
            int row = bm + r;
            float4 v = make_float4(0.f, 0.f, 0.f, 0.f);
            if (row < M_NODES)
                v = *reinterpret_cast<const float4*>(x + (size_t)row * DCH + kk + j * 4);
            ar[l] = v;
            br[l] = *reinterpret_cast<const uint2*>(wsrc + (size_t)(bn + r) * DCH + kk + j * 4);
        }
    };

    auto sts = [&](int kt, int buf) {
        const bool hi = ((kt >> 3) < 2);
#pragma unroll
        for (int l = 0; l < 4; l++) {
            int t = tid + l * 256, r = t >> 3, j = t & 7;
            float4 v = ar[l];
            __nv_bfloat162 h01 = __floats2bfloat162_rn(v.x, v.y);
            __nv_bfloat162 h23 = __floats2bfloat162_rn(v.z, v.w);
            __nv_bfloat162 p0, p1;
            if (hi) { p0 = h01; p1 = h23; }
            else {
                p0 = __floats2bfloat162_rn(v.x - __bfloat162float(h01.x),
                                           v.y - __bfloat162float(h01.y));
                p1 = __floats2bfloat162_rn(v.z - __bfloat162float(h23.x),
                                           v.w - __bfloat162float(h23.y));
            }
            *reinterpret_cast<uint2*>(&As[buf][r * AS_LD + j * 4]) =
                make_uint2(*reinterpret_cast<uint32_t*>(&p0), *reinterpret_cast<uint32_t*>(&p1));
            *reinterpret_cast<uint2*>(&Bs[buf][r * AS_LD + j * 4]) = br[l];
        }
    };

    auto compute = [&](int buf) {
        const uint32_t as_b = smem_u32(&As[buf][0]);
        const uint32_t bs_b = smem_u32(&Bs[buf][0]);
#pragma unroll
        for (int ks = 0; ks < 2; ks++) {
            const int k0 = ks * 16;
            uint32_t afrag[2][4];
#pragma unroll
            for (int mt = 0; mt < 2; mt++)
                ldsm_x4(afrag[mt], as_b + 2u * ((mw * 32 + mt * 16 + (lane & 15)) * AS_LD +
                                                (lane >> 4) * 8 + k0));
            uint32_t bfrag[8][2];
#pragma unroll
            for (int nt = 0; nt < 8; nt++)
                ldsm_x2(bfrag[nt], bs_b + 2u * ((nw * 64 + nt * 8 + (lane & 7)) * AS_LD +
                                                ((lane >> 3) & 1) * 8 + k0));
#pragma unroll
            for (int mt = 0; mt < 2; mt++)
#pragma unroll
                for (int nt = 0; nt < 8; nt++)
                    mma_bf16(acc[mt][nt], afrag[mt], bfrag[nt]);
        }
    };

    load_g(0);
    sts(0, 0);
    __syncthreads();

#pragma unroll 1
    for (int kt = 0; kt < 24; kt++) {
        const int buf = kt & 1;
        if (kt < 23) load_g(kt + 1);
        compute(buf);
        if (kt < 23) sts(kt + 1, buf ^ 1);
        __syncthreads();
    }

#pragma unroll
    for (int mt = 0; mt < 2; mt++) {
        const int m0 = bm + mw * 32 + mt * 16 + (lane >> 2);
#pragma unroll
        for (int nt = 0; nt < 8; nt++) {
            const int n = bn + nw * 64 + nt * 8 + (lane & 3) * 2;
            if (m0 < M_NODES)
                *reinterpret_cast<float2*>(&g_h[(size_t)m0 * DCH + n]) =
                    make_float2(acc[mt][nt][0], acc[mt][nt][1]);
            if (m0 + 8 < M_NODES)
                *reinterpret_cast<float2*>(&g_h[(size_t)(m0 + 8) * DCH + n]) =
                    make_float2(acc[mt][nt][2], acc[mt][nt][3]);
        }
    }
}

// ===================== gather + BALANCED-PIPE selection network ==============
// CE : classic alu-pipe comparator (2 x FMNMX)
// CEB: balanced comparator — mn = fminf (alu, exact),
//      mx = (a+b) - mn (2 x FADD on the fma pipe, <= 2 ulp error).
// alu/fma pipes are separate, each rt=2, issue 1/cyc -> mixing ~doubles tput.
#define CE(a, b)  { float _mn = fminf(v[a], v[b]); \
                    float _mx = fmaxf(v[a], v[b]); \
                    v[a] = _mn; v[b] = _mx; }
#define CEB(a, b) { float _s = v[a] + v[b]; \
                    float _mn = fminf(v[a], v[b]); \
                    v[a] = _mn; v[b] = _s - _mn; }

// Batcher odd-even mergesort-16 (63 comparators), comparator macro split:
// C1 = first 32 (through p=4,k=2), C2 = last 31.
#define OEMS16(o, C1, C2) \
    /* p=1,k=1 */ \
    C1(o+0,o+1)  C1(o+2,o+3)   C1(o+4,o+5)   C1(o+6,o+7) \
    C1(o+8,o+9)  C1(o+10,o+11) C1(o+12,o+13) C1(o+14,o+15) \
    /* p=2,k=2 */ \
    C1(o+0,o+2)  C1(o+1,o+3)   C1(o+4,o+6)   C1(o+5,o+7) \
    C1(o+8,o+10) C1(o+9,o+11)  C1(o+12,o+14) C1(o+13,o+15) \
    /* p=2,k=1 */ \
    C1(o+1,o+2)  C1(o+5,o+6)   C1(o+9,o+10)  C1(o+13,o+14) \
    /* p=4,k=4 */ \
    C1(o+0,o+4)  C1(o+1,o+5)   C1(o+2,o+6)   C1(o+3,o+7) \
    C1(o+8,o+12) C1(o+9,o+13)  C1(o+10,o+14) C1(o+11,o+15) \
    /* p=4,k=2 */ \
    C1(o+2,o+4)  C1(o+3,o+5)   C1(o+10,o+12) C1(o+11,o+13) \
    /* p=4,k=1 */ \
    C2(o+1,o+2)  C2(o+3,o+4)   C2(o+5,o+6) \
    C2(o+9,o+10) C2(o+11,o+12) C2(o+13,o+14) \
    /* p=8,k=8 */ \
    C2(o+0,o+8)  C2(o+1,o+9)   C2(o+2,o+10)  C2(o+3,o+11) \
    C2(o+4,o+12) C2(o+5,o+13)  C2(o+6,o+14)  C2(o+7,o+15) \
    /* p=8,k=4 */ \
    C2(o+4,o+8)  C2(o+5,o+9)   C2(o+6,o+10)  C2(o+7,o+11) \
    /* p=8,k=2 */ \
    C2(o+2,o+4)  C2(o+3,o+5)   C2(o+6,o+8) \
    C2(o+7,o+9)  C2(o+10,o+12) C2(o+11,o+13) \
    /* p=8,k=1 */ \
    C2(o+1,o+2)  C2(o+3,o+4)   C2(o+5,o+6)   C2(o+7,o+8) \
    C2(o+9,o+10) C2(o+11,o+12) C2(o+13,o+14)

__global__ void __launch_bounds__(256) gather_trim(
    const void* __restrict__ nbrs_raw,
    float* __restrict__ out)
{
    __shared__ int sn[K_NBR];

    const int node = blockIdx.x;
    const int tid  = threadIdx.x;

    if (tid < K_NBR) {
        const int* w = reinterpret_cast<const int*>(nbrs_raw);
        unsigned m = __ballot_sync(0xffffffffu, w[2 * tid + 1] == 0);
        bool is64 = (m == 0xffffffffu);
        long long idx = is64
            ? reinterpret_cast<const long long*>(nbrs_raw)[(size_t)node * K_NBR + tid]
            : (long long)reinterpret_cast<const int*>(nbrs_raw)[(size_t)node * K_NBR + tid];
        sn[tid] = (int)idx * DCH;
    }
    __syncthreads();

    float v[K_NBR];
#pragma unroll
    for (int k = 0; k < K_NBR; k++)
        v[k] = __ldg(&g_h[sn[k] + tid]);

    // sort halves: 63 CEB + (32 CEB + 31 CE)  -> 111 CEB + 31 CE total w/ cleaner
    OEMS16(0, CEB, CEB)
    OEMS16(16, CEB, CE)

    // half-cleaner (16 CEB): v[0..15] = 16 smallest (bitonic), v[16..31] largest
#pragma unroll
    for (int i = 0; i < 16; i++) {
        float _s  = v[i] + v[31 - i];
        float _mn = fminf(v[i], v[31 - i]);
        v[i]      = _mn;
        v[31 - i] = _s - _mn;
    }

    // ranks 14,15 = top-2 of bitonic lower (alu max-reductions)
#pragma unroll
    for (int j = 8; j >= 2; j >>= 1)
#pragma unroll
        for (int i = 0; i < j; i++)
            v[i] = fmaxf(v[i], v[i + j]);

    // ranks 16,17 = bottom-2 of bitonic upper (alu min-reductions)
#pragma unroll
    for (int j = 8; j >= 2; j >>= 1)
#pragma unroll
        for (int i = 0; i < j; i++)
            v[16 + i] = fminf(v[16 + i], v[16 + i + j]);

    out[(size_t)node * DCH + tid] = (v[0] + v[1] + v[16] + v[17]) * 0.25f;
}

// ===================== launch ===============================================
extern "C" void kernel_launch(void* const* d_in, const int* in_sizes, int n_in,
                              void* d_out, int out_size)
{
    const float* x    = nullptr;
    const void*  nbrs = nullptr;
    const float* W    = nullptr;

    for (int i = 0; i < n_in; i++) {
        if      (in_sizes[i] == M_NODES * DCH)   x    = (const float*)d_in[i];
        else if (in_sizes[i] == M_NODES * K_NBR) nbrs = d_in[i];
        else if (in_sizes[i] == DCH * DCH)       W    = (const float*)d_in[i];
    }
    if (!x)    x    = (const float*)d_in[0];
    if (!nbrs) nbrs = d_in[1];
    if (!W)    W    = (const float*)d_in[2];

    convert_w<<<(DCH * DCH / 4 + 255) / 256, 256>>>(W);

    dim3 ggrid((M_NODES + 127) / 128, 2);
    gemm_mma<<<ggrid, 256>>>(x);

    gather_trim<<<M_NODES, 256>>>(nbrs, (float*)d_out);
}

// round 8
// speedup vs baseline: 1.3292x; 1.1864x over previous
#include <cuda_runtime.h>
#include <cuda_bf16.h>
#include <cstdint>

#define M_NODES 50000
#define K_NBR   32
#define DCH     256

__device__ float         g_h[M_NODES * DCH];
__device__ __nv_bfloat16 g_whi[DCH * DCH];
__device__ __nv_bfloat16 g_wlo[DCH * DCH];

// ===================== W split (tiny) ========================================
__global__ void __launch_bounds__(256) convert_w(const float* __restrict__ w) {
    size_t i4 = (size_t)blockIdx.x * 256 + threadIdx.x;
    if (i4 * 4 >= (size_t)DCH * DCH) return;
    float4 f = *reinterpret_cast<const float4*>(w + i4 * 4);
    __nv_bfloat162 h01 = __floats2bfloat162_rn(f.x, f.y);
    __nv_bfloat162 h23 = __floats2bfloat162_rn(f.z, f.w);
    __nv_bfloat162 l01 = __floats2bfloat162_rn(f.x - __bfloat162float(h01.x),
                                               f.y - __bfloat162float(h01.y));
    __nv_bfloat162 l23 = __floats2bfloat162_rn(f.z - __bfloat162float(h23.x),
                                               f.w - __bfloat162float(h23.y));
    reinterpret_cast<uint2*>(g_whi)[i4] =
        make_uint2(*reinterpret_cast<uint32_t*>(&h01), *reinterpret_cast<uint32_t*>(&h23));
    reinterpret_cast<uint2*>(g_wlo)[i4] =
        make_uint2(*reinterpret_cast<uint32_t*>(&l01), *reinterpret_cast<uint32_t*>(&l23));
}

// ===================== mma.sync bf16 split GEMM (proven R5 form) =============
#define AS_LD 40

__device__ __forceinline__ uint32_t smem_u32(const void* p) {
    uint32_t a;
    asm("{ .reg .u64 t; cvta.to.shared.u64 t, %1; cvt.u32.u64 %0, t; }" : "=r"(a) : "l"(p));
    return a;
}
__device__ __forceinline__ void ldsm_x4(uint32_t* r, uint32_t addr) {
    asm volatile("ldmatrix.sync.aligned.m8n8.x4.shared.b16 {%0,%1,%2,%3}, [%4];"
                 : "=r"(r[0]), "=r"(r[1]), "=r"(r[2]), "=r"(r[3]) : "r"(addr));
}
__device__ __forceinline__ void ldsm_x2(uint32_t* r, uint32_t addr) {
    asm volatile("ldmatrix.sync.aligned.m8n8.x2.shared.b16 {%0,%1}, [%2];"
                 : "=r"(r[0]), "=r"(r[1]) : "r"(addr));
}
__device__ __forceinline__ void mma_bf16(float* d, const uint32_t* a, const uint32_t* b) {
    asm volatile(
        "mma.sync.aligned.m16n8k16.row.col.f32.bf16.bf16.f32 "
        "{%0,%1,%2,%3}, {%4,%5,%6,%7}, {%8,%9}, {%0,%1,%2,%3};"
        : "+f"(d[0]), "+f"(d[1]), "+f"(d[2]), "+f"(d[3])
        : "r"(a[0]), "r"(a[1]), "r"(a[2]), "r"(a[3]), "r"(b[0]), "r"(b[1]));
}

__global__ void __launch_bounds__(256) gemm_mma(const float* __restrict__ x) {
    __shared__ __align__(16) __nv_bfloat16 As[2][128 * AS_LD];
    __shared__ __align__(16) __nv_bfloat16 Bs[2][128 * AS_LD];

    const int tid  = threadIdx.x;
    const int bm   = blockIdx.x * 128;
    const int bn   = blockIdx.y * 128;
    const int warp = tid >> 5, lane = tid & 31;
    const int mw   = warp >> 1, nw = warp & 1;

    float acc[2][8][4];
#pragma unroll
    for (int mt = 0; mt < 2; mt++)
#pragma unroll
        for (int nt = 0; nt < 8; nt++)
#pragma unroll
            for (int q = 0; q < 4; q++) acc[mt][nt][q] = 0.0f;

    float4 ar[4];
    uint2  br[4];

    auto load_g = [&](int kt) {
        const int seg = kt >> 3;
        const int kk  = (kt & 7) * 32;
        const __nv_bfloat16* wsrc = (seg == 1) ? g_wlo : g_whi;
#pragma unroll
        for (int l = 0; l < 4; l++) {
            int t = tid + l * 256, r = t >> 3, j = t & 7;
            int row = bm + r;
            float4 v = make_float4(0.f, 0.f, 0.f, 0.f);
            if (row < M_NODES)
                v = *reinterpret_cast<const float4*>(x + (size_t)row * DCH + kk + j * 4);
            ar[l] = v;
            br[l] = *reinterpret_cast<const uint2*>(wsrc + (size_t)(bn + r) * DCH + kk + j * 4);
        }
    };

    auto sts = [&](int kt, int buf) {
        const bool hi = ((kt >> 3) < 2);
#pragma unroll
        for (int l = 0; l < 4; l++) {
            int t = tid + l * 256, r = t >> 3, j = t & 7;
            float4 v = ar[l];
            __nv_bfloat162 h01 = __floats2bfloat162_rn(v.x, v.y);
            __nv_bfloat162 h23 = __floats2bfloat162_rn(v.z, v.w);
            __nv_bfloat162 p0, p1;
            if (hi) { p0 = h01; p1 = h23; }
            else {
                p0 = __floats2bfloat162_rn(v.x - __bfloat162float(h01.x),
                                           v.y - __bfloat162float(h01.y));
                p1 = __floats2bfloat162_rn(v.z - __bfloat162float(h23.x),
                                           v.w - __bfloat162float(h23.y));
            }
            *reinterpret_cast<uint2*>(&As[buf][r * AS_LD + j * 4]) =
                make_uint2(*reinterpret_cast<uint32_t*>(&p0), *reinterpret_cast<uint32_t*>(&p1));
            *reinterpret_cast<uint2*>(&Bs[buf][r * AS_LD + j * 4]) = br[l];
        }
    };

    auto compute = [&](int buf) {
        const uint32_t as_b = smem_u32(&As[buf][0]);
        const uint32_t bs_b = smem_u32(&Bs[buf][0]);
#pragma unroll
        for (int ks = 0; ks < 2; ks++) {
            const int k0 = ks * 16;
            uint32_t afrag[2][4];
#pragma unroll
            for (int mt = 0; mt < 2; mt++)
                ldsm_x4(afrag[mt], as_b + 2u * ((mw * 32 + mt * 16 + (lane & 15)) * AS_LD +
                                                (lane >> 4) * 8 + k0));
            uint32_t bfrag[8][2];
#pragma unroll
            for (int nt = 0; nt < 8; nt++)
                ldsm_x2(bfrag[nt], bs_b + 2u * ((nw * 64 + nt * 8 + (lane & 7)) * AS_LD +
                                                ((lane >> 3) & 1) * 8 + k0));
#pragma unroll
            for (int mt = 0; mt < 2; mt++)
#pragma unroll
                for (int nt = 0; nt < 8; nt++)
                    mma_bf16(acc[mt][nt], afrag[mt], bfrag[nt]);
        }
    };

    load_g(0);
    sts(0, 0);
    __syncthreads();

#pragma unroll 1
    for (int kt = 0; kt < 24; kt++) {
        const int buf = kt & 1;
        if (kt < 23) load_g(kt + 1);
        compute(buf);
        if (kt < 23) sts(kt + 1, buf ^ 1);
        __syncthreads();
    }

#pragma unroll
    for (int mt = 0; mt < 2; mt++) {
        const int m0 = bm + mw * 32 + mt * 16 + (lane >> 2);
#pragma unroll
        for (int nt = 0; nt < 8; nt++) {
            const int n = bn + nw * 64 + nt * 8 + (lane & 3) * 2;
            if (m0 < M_NODES)
                *reinterpret_cast<float2*>(&g_h[(size_t)m0 * DCH + n]) =
                    make_float2(acc[mt][nt][0], acc[mt][nt][1]);
            if (m0 + 8 < M_NODES)
                *reinterpret_cast<float2*>(&g_h[(size_t)(m0 + 8) * DCH + n]) =
                    make_float2(acc[mt][nt][2], acc[mt][nt][3]);
        }
    }
}

// ===================== gather: f32x2 packed 2-channel selection ==============
// Thread owns channels (2t, 2t+1) as float2. Comparator (both channels):
//   s  = add.rn.f32x2(a, b)            (1 fma-pipe instr, both lanes)
//   mn = fminf per channel             (2 alu FMNMX)
//   mx = fma.rn.f32x2(mn, -1, s)       (1 fma-pipe FFMA2)
// 4 instr / 2 channels vs 6 for scalar CEB.
#define CE2(a, b) {                                                             \
    unsigned long long _va = *reinterpret_cast<unsigned long long*>(&v[a]);     \
    unsigned long long _vb = *reinterpret_cast<unsigned long long*>(&v[b]);     \
    unsigned long long _s, _mx;                                                 \
    asm("add.rn.f32x2 %0, %1, %2;" : "=l"(_s) : "l"(_va), "l"(_vb));            \
    v[a].x = fminf(v[a].x, v[b].x);                                             \
    v[a].y = fminf(v[a].y, v[b].y);                                             \
    unsigned long long _mn = *reinterpret_cast<unsigned long long*>(&v[a]);     \
    asm("fma.rn.f32x2 %0, %1, %2, %3;" : "=l"(_mx) : "l"(_mn), "l"(neg1), "l"(_s)); \
    *reinterpret_cast<unsigned long long*>(&v[b]) = _mx; }

// Batcher odd-even mergesort-16, ascending, 63 comparators (literal indices)
#define OEMS16(o, C) \
    C(o+0,o+1)  C(o+2,o+3)   C(o+4,o+5)   C(o+6,o+7) \
    C(o+8,o+9)  C(o+10,o+11) C(o+12,o+13) C(o+14,o+15) \
    C(o+0,o+2)  C(o+1,o+3)   C(o+4,o+6)   C(o+5,o+7) \
    C(o+8,o+10) C(o+9,o+11)  C(o+12,o+14) C(o+13,o+15) \
    C(o+1,o+2)  C(o+5,o+6)   C(o+9,o+10)  C(o+13,o+14) \
    C(o+0,o+4)  C(o+1,o+5)   C(o+2,o+6)   C(o+3,o+7) \
    C(o+8,o+12) C(o+9,o+13)  C(o+10,o+14) C(o+11,o+15) \
    C(o+2,o+4)  C(o+3,o+5)   C(o+10,o+12) C(o+11,o+13) \
    C(o+1,o+2)  C(o+3,o+4)   C(o+5,o+6) \
    C(o+9,o+10) C(o+11,o+12) C(o+13,o+14) \
    C(o+0,o+8)  C(o+1,o+9)   C(o+2,o+10)  C(o+3,o+11) \
    C(o+4,o+12) C(o+5,o+13)  C(o+6,o+14)  C(o+7,o+15) \
    C(o+4,o+8)  C(o+5,o+9)   C(o+6,o+10)  C(o+7,o+11) \
    C(o+2,o+4)  C(o+3,o+5)   C(o+6,o+8) \
    C(o+7,o+9)  C(o+10,o+12) C(o+11,o+13) \
    C(o+1,o+2)  C(o+3,o+4)   C(o+5,o+6)   C(o+7,o+8) \
    C(o+9,o+10) C(o+11,o+12) C(o+13,o+14)

__global__ void __launch_bounds__(128) gather_trim(
    const void* __restrict__ nbrs_raw,
    float* __restrict__ out)
{
    __shared__ int sn[K_NBR];

    const int node = blockIdx.x;
    const int tid  = threadIdx.x;
    const unsigned long long neg1 = 0xBF800000BF800000ULL;  // (-1.0f, -1.0f)

    if (tid < K_NBR) {
        const int* w = reinterpret_cast<const int*>(nbrs_raw);
        unsigned m = __ballot_sync(0xffffffffu, w[2 * tid + 1] == 0);
        bool is64 = (m == 0xffffffffu);
        long long idx = is64
            ? reinterpret_cast<const long long*>(nbrs_raw)[(size_t)node * K_NBR + tid]
            : (long long)reinterpret_cast<const int*>(nbrs_raw)[(size_t)node * K_NBR + tid];
        sn[tid] = (int)idx * DCH;
    }
    __syncthreads();

    // thread owns channels 2*tid, 2*tid+1
    float2 v[K_NBR];
#pragma unroll
    for (int k = 0; k < K_NBR; k++)
        v[k] = *reinterpret_cast<const float2*>(&g_h[sn[k] + 2 * tid]);

    OEMS16(0, CE2)
    OEMS16(16, CE2)

    // half-cleaner: v[0..15] = 16 smallest (bitonic), v[16..31] = 16 largest
#pragma unroll
    for (int i = 0; i < 16; i++) {
        unsigned long long _va = *reinterpret_cast<unsigned long long*>(&v[i]);
        unsigned long long _vb = *reinterpret_cast<unsigned long long*>(&v[31 - i]);
        unsigned long long _s, _mx;
        asm("add.rn.f32x2 %0, %1, %2;" : "=l"(_s) : "l"(_va), "l"(_vb));
        v[i].x = fminf(v[i].x, v[31 - i].x);
        v[i].y = fminf(v[i].y, v[31 - i].y);
        unsigned long long _mn = *reinterpret_cast<unsigned long long*>(&v[i]);
        asm("fma.rn.f32x2 %0, %1, %2, %3;" : "=l"(_mx) : "l"(_mn), "l"(neg1), "l"(_s));
        *reinterpret_cast<unsigned long long*>(&v[31 - i]) = _mx;
    }

    // ranks 14,15 = top-2 of bitonic lower (max-reductions)
#pragma unroll
    for (int j = 8; j >= 2; j >>= 1)
#pragma unroll
        for (int i = 0; i < j; i++) {
            v[i].x = fmaxf(v[i].x, v[i + j].x);
            v[i].y = fmaxf(v[i].y, v[i + j].y);
        }

    // ranks 16,17 = bottom-2 of bitonic upper (min-reductions)
#pragma unroll
    for (int j = 8; j >= 2; j >>= 1)
#pragma unroll
        for (int i = 0; i < j; i++) {
            v[16 + i].x = fminf(v[16 + i].x, v[16 + i + j].x);
            v[16 + i].y = fminf(v[16 + i].y, v[16 + i + j].y);
        }

    // mean of the 4 kept ranks, packed
    unsigned long long t0, t1, t2;
    unsigned long long a0 = *reinterpret_cast<unsigned long long*>(&v[0]);
    unsigned long long a1 = *reinterpret_cast<unsigned long long*>(&v[1]);
    unsigned long long b0 = *reinterpret_cast<unsigned long long*>(&v[16]);
    unsigned long long b1 = *reinterpret_cast<unsigned long long*>(&v[17]);
    asm("add.rn.f32x2 %0, %1, %2;" : "=l"(t0) : "l"(a0), "l"(a1));
    asm("add.rn.f32x2 %0, %1, %2;" : "=l"(t1) : "l"(b0), "l"(b1));
    asm("add.rn.f32x2 %0, %1, %2;" : "=l"(t2) : "l"(t0), "l"(t1));
    float2 s4 = *reinterpret_cast<float2*>(&t2);
    float2 r  = make_float2(s4.x * 0.25f, s4.y * 0.25f);

    *reinterpret_cast<float2*>(&out[(size_t)node * DCH + 2 * tid]) = r;
}

// ===================== launch ===============================================
extern "C" void kernel_launch(void* const* d_in, const int* in_sizes, int n_in,
                              void* d_out, int out_size)
{
    const float* x    = nullptr;
    const void*  nbrs = nullptr;
    const float* W    = nullptr;

    for (int i = 0; i < n_in; i++) {
        if      (in_sizes[i] == M_NODES * DCH)   x    = (const float*)d_in[i];
        else if (in_sizes[i] == M_NODES * K_NBR) nbrs = d_in[i];
        else if (in_sizes[i] == DCH * DCH)       W    = (const float*)d_in[i];
    }
    if (!x)    x    = (const float*)d_in[0];
    if (!nbrs) nbrs = d_in[1];
    if (!W)    W    = (const float*)d_in[2];

    convert_w<<<(DCH * DCH / 4 + 255) / 256, 256>>>(W);

    dim3 ggrid((M_NODES + 127) / 128, 2);
    gemm_mma<<<ggrid, 256>>>(x);

    gather_trim<<<M_NODES, 128>>>(nbrs, (float*)d_out);
}

// round 9
// speedup vs baseline: 1.6172x; 1.2167x over previous
#include <cuda_runtime.h>
#include <cuda_bf16.h>
#include <cuda_fp16.h>
#include <cstdint>

#define M_NODES 50000
#define K_NBR   32
#define DCH     256

__device__ __half         g_hh[M_NODES * DCH];   // h stored fp16
__device__ __nv_bfloat16  g_whi[DCH * DCH];
__device__ __nv_bfloat16  g_wlo[DCH * DCH];

// ===================== W split (tiny) ========================================
__global__ void __launch_bounds__(256) convert_w(const float* __restrict__ w) {
    size_t i4 = (size_t)blockIdx.x * 256 + threadIdx.x;
    if (i4 * 4 >= (size_t)DCH * DCH) return;
    float4 f = *reinterpret_cast<const float4*>(w + i4 * 4);
    __nv_bfloat162 h01 = __floats2bfloat162_rn(f.x, f.y);
    __nv_bfloat162 h23 = __floats2bfloat162_rn(f.z, f.w);
    __nv_bfloat162 l01 = __floats2bfloat162_rn(f.x - __bfloat162float(h01.x),
                                               f.y - __bfloat162float(h01.y));
    __nv_bfloat162 l23 = __floats2bfloat162_rn(f.z - __bfloat162float(h23.x),
                                               f.w - __bfloat162float(h23.y));
    reinterpret_cast<uint2*>(g_whi)[i4] =
        make_uint2(*reinterpret_cast<uint32_t*>(&h01), *reinterpret_cast<uint32_t*>(&h23));
    reinterpret_cast<uint2*>(g_wlo)[i4] =
        make_uint2(*reinterpret_cast<uint32_t*>(&l01), *reinterpret_cast<uint32_t*>(&l23));
}

// ===================== mma.sync bf16 split GEMM (R5 form) ====================
#define AS_LD 40

__device__ __forceinline__ uint32_t smem_u32(const void* p) {
    uint32_t a;
    asm("{ .reg .u64 t; cvta.to.shared.u64 t, %1; cvt.u32.u64 %0, t; }" : "=r"(a) : "l"(p));
    return a;
}
__device__ __forceinline__ void ldsm_x4(uint32_t* r, uint32_t addr) {
    asm volatile("ldmatrix.sync.aligned.m8n8.x4.shared.b16 {%0,%1,%2,%3}, [%4];"
                 : "=r"(r[0]), "=r"(r[1]), "=r"(r[2]), "=r"(r[3]) : "r"(addr));
}
__device__ __forceinline__ void ldsm_x2(uint32_t* r, uint32_t addr) {
    asm volatile("ldmatrix.sync.aligned.m8n8.x2.shared.b16 {%0,%1}, [%2];"
                 : "=r"(r[0]), "=r"(r[1]) : "r"(addr));
}
__device__ __forceinline__ void mma_bf16(float* d, const uint32_t* a, const uint32_t* b) {
    asm volatile(
        "mma.sync.aligned.m16n8k16.row.col.f32.bf16.bf16.f32 "
        "{%0,%1,%2,%3}, {%4,%5,%6,%7}, {%8,%9}, {%0,%1,%2,%3};"
        : "+f"(d[0]), "+f"(d[1]), "+f"(d[2]), "+f"(d[3])
        : "r"(a[0]), "r"(a[1]), "r"(a[2]), "r"(a[3]), "r"(b[0]), "r"(b[1]));
}

__global__ void __launch_bounds__(256) gemm_mma(const float* __restrict__ x) {
    __shared__ __align__(16) __nv_bfloat16 As[2][128 * AS_LD];
    __shared__ __align__(16) __nv_bfloat16 Bs[2][128 * AS_LD];

    const int tid  = threadIdx.x;
    const int bm   = blockIdx.x * 128;
    const int bn   = blockIdx.y * 128;
    const int warp = tid >> 5, lane = tid & 31;
    const int mw   = warp >> 1, nw = warp & 1;

    float acc[2][8][4];
#pragma unroll
    for (int mt = 0; mt < 2; mt++)
#pragma unroll
        for (int nt = 0; nt < 8; nt++)
#pragma unroll
            for (int q = 0; q < 4; q++) acc[mt][nt][q] = 0.0f;

    float4 ar[4];
    uint2  br[4];

    auto load_g = [&](int kt) {
        const int seg = kt >> 3;
        const int kk  = (kt & 7) * 32;
        const __nv_bfloat16* wsrc = (seg == 1) ? g_wlo : g_whi;
#pragma unroll
        for (int l = 0; l < 4; l++) {
            int t = tid + l * 256, r = t >> 3, j = t & 7;
            int row = bm + r;
            float4 v = make_float4(0.f, 0.f, 0.f, 0.f);
            if (row < M_NODES)
                v = *reinterpret_cast<const float4*>(x + (size_t)row * DCH + kk + j * 4);
            ar[l] = v;
            br[l] = *reinterpret_cast<const uint2*>(wsrc + (size_t)(bn + r) * DCH + kk + j * 4);
        }
    };

    auto sts = [&](int kt, int buf) {
        const bool hi = ((kt >> 3) < 2);
#pragma unroll
        for (int l = 0; l < 4; l++) {
            int t = tid + l * 256, r = t >> 3, j = t & 7;
            float4 v = ar[l];
            __nv_bfloat162 h01 = __floats2bfloat162_rn(v.x, v.y);
            __nv_bfloat162 h23 = __floats2bfloat162_rn(v.z, v.w);
            __nv_bfloat162 p0, p1;
            if (hi) { p0 = h01; p1 = h23; }
            else {
                p0 = __floats2bfloat162_rn(v.x - __bfloat162float(h01.x),
                                           v.y - __bfloat162float(h01.y));
                p1 = __floats2bfloat162_rn(v.z - __bfloat162float(h23.x),
                                           v.w - __bfloat162float(h23.y));
            }
            *reinterpret_cast<uint2*>(&As[buf][r * AS_LD + j * 4]) =
                make_uint2(*reinterpret_cast<uint32_t*>(&p0), *reinterpret_cast<uint32_t*>(&p1));
            *reinterpret_cast<uint2*>(&Bs[buf][r * AS_LD + j * 4]) = br[l];
        }
    };

    auto compute = [&](int buf) {
        const uint32_t as_b = smem_u32(&As[buf][0]);
        const uint32_t bs_b = smem_u32(&Bs[buf][0]);
#pragma unroll
        for (int ks = 0; ks < 2; ks++) {
            const int k0 = ks * 16;
            uint32_t afrag[2][4];
#pragma unroll
            for (int mt = 0; mt < 2; mt++)
                ldsm_x4(afrag[mt], as_b + 2u * ((mw * 32 + mt * 16 + (lane & 15)) * AS_LD +
                                                (lane >> 4) * 8 + k0));
            uint32_t bfrag[8][2];
#pragma unroll
            for (int nt = 0; nt < 8; nt++)
                ldsm_x2(bfrag[nt], bs_b + 2u * ((nw * 64 + nt * 8 + (lane & 7)) * AS_LD +
                                                ((lane >> 3) & 1) * 8 + k0));
#pragma unroll
            for (int mt = 0; mt < 2; mt++)
#pragma unroll
                for (int nt = 0; nt < 8; nt++)
                    mma_bf16(acc[mt][nt], afrag[mt], bfrag[nt]);
        }
    };

    load_g(0);
    sts(0, 0);
    __syncthreads();

#pragma unroll 1
    for (int kt = 0; kt < 24; kt++) {
        const int buf = kt & 1;
        if (kt < 23) load_g(kt + 1);
        compute(buf);
        if (kt < 23) sts(kt + 1, buf ^ 1);
        __syncthreads();
    }

    // epilogue: acc -> g_hh (fp16 packed pairs; n is even so 4B aligned)
#pragma unroll
    for (int mt = 0; mt < 2; mt++) {
        const int m0 = bm + mw * 32 + mt * 16 + (lane >> 2);
#pragma unroll
        for (int nt = 0; nt < 8; nt++) {
            const int n = bn + nw * 64 + nt * 8 + (lane & 3) * 2;
            __half2 p01 = __floats2half2_rn(acc[mt][nt][0], acc[mt][nt][1]);
            __half2 p23 = __floats2half2_rn(acc[mt][nt][2], acc[mt][nt][3]);
            if (m0 < M_NODES)
                *reinterpret_cast<__half2*>(&g_hh[(size_t)m0 * DCH + n]) = p01;
            if (m0 + 8 < M_NODES)
                *reinterpret_cast<__half2*>(&g_hh[(size_t)(m0 + 8) * DCH + n]) = p23;
        }
    }
}

// ===================== gather: f16x2 packed 2-channel selection ==============
// Thread owns channels (2t, 2t+1) as one __half2. Comparator = HMNMX2 pair:
// 2 instructions / 2 channels. min/max are EXACT in fp16 (no error growth).
#define CE2H(a, b) { __half2 _mn = __hmin2(v[a], v[b]); \
                     __half2 _mx = __hmax2(v[a], v[b]); \
                     v[a] = _mn; v[b] = _mx; }

// Batcher odd-even mergesort-16, ascending, 63 comparators (literal indices)
#define OEMS16(o, C) \
    C(o+0,o+1)  C(o+2,o+3)   C(o+4,o+5)   C(o+6,o+7) \
    C(o+8,o+9)  C(o+10,o+11) C(o+12,o+13) C(o+14,o+15) \
    C(o+0,o+2)  C(o+1,o+3)   C(o+4,o+6)   C(o+5,o+7) \
    C(o+8,o+10) C(o+9,o+11)  C(o+12,o+14) C(o+13,o+15) \
    C(o+1,o+2)  C(o+5,o+6)   C(o+9,o+10)  C(o+13,o+14) \
    C(o+0,o+4)  C(o+1,o+5)   C(o+2,o+6)   C(o+3,o+7) \
    C(o+8,o+12) C(o+9,o+13)  C(o+10,o+14) C(o+11,o+15) \
    C(o+2,o+4)  C(o+3,o+5)   C(o+10,o+12) C(o+11,o+13) \
    C(o+1,o+2)  C(o+3,o+4)   C(o+5,o+6) \
    C(o+9,o+10) C(o+11,o+12) C(o+13,o+14) \
    C(o+0,o+8)  C(o+1,o+9)   C(o+2,o+10)  C(o+3,o+11) \
    C(o+4,o+12) C(o+5,o+13)  C(o+6,o+14)  C(o+7,o+15) \
    C(o+4,o+8)  C(o+5,o+9)   C(o+6,o+10)  C(o+7,o+11) \
    C(o+2,o+4)  C(o+3,o+5)   C(o+6,o+8) \
    C(o+7,o+9)  C(o+10,o+12) C(o+11,o+13) \
    C(o+1,o+2)  C(o+3,o+4)   C(o+5,o+6)   C(o+7,o+8) \
    C(o+9,o+10) C(o+11,o+12) C(o+13,o+14)

__global__ void __launch_bounds__(128) gather_trim(
    const void* __restrict__ nbrs_raw,
    float* __restrict__ out)
{
    __shared__ int sn[K_NBR];

    const int node = blockIdx.x;
    const int tid  = threadIdx.x;

    if (tid < K_NBR) {
        const int* w = reinterpret_cast<const int*>(nbrs_raw);
        unsigned m = __ballot_sync(0xffffffffu, w[2 * tid + 1] == 0);
        bool is64 = (m == 0xffffffffu);
        long long idx = is64
            ? reinterpret_cast<const long long*>(nbrs_raw)[(size_t)node * K_NBR + tid]
            : (long long)reinterpret_cast<const int*>(nbrs_raw)[(size_t)node * K_NBR + tid];
        sn[tid] = (int)idx * DCH;
    }
    __syncthreads();

    // thread owns channels 2*tid, 2*tid+1 (one half2 = one 32-bit load)
    __half2 v[K_NBR];
#pragma unroll
    for (int k = 0; k < K_NBR; k++)
        v[k] = *reinterpret_cast<const __half2*>(&g_hh[sn[k] + 2 * tid]);

    OEMS16(0, CE2H)
    OEMS16(16, CE2H)

    // half-cleaner: v[0..15] = 16 smallest (bitonic), v[16..31] = 16 largest
#pragma unroll
    for (int i = 0; i < 16; i++) {
        __half2 a = v[i], b = v[31 - i];
        v[i]      = __hmin2(a, b);
        v[31 - i] = __hmax2(a, b);
    }

    // ranks 14,15 = top-2 of bitonic lower (max-reductions)
#pragma unroll
    for (int j = 8; j >= 2; j >>= 1)
#pragma unroll
        for (int i = 0; i < j; i++)
            v[i] = __hmax2(v[i], v[i + j]);

    // ranks 16,17 = bottom-2 of bitonic upper (min-reductions)
#pragma unroll
    for (int j = 8; j >= 2; j >>= 1)
#pragma unroll
        for (int i = 0; i < j; i++)
            v[16 + i] = __hmin2(v[16 + i], v[16 + i + j]);

    // mean of the 4 kept ranks in fp32 (unpack first: exact)
    float2 f0 = __half22float2(v[0]);
    float2 f1 = __half22float2(v[1]);
    float2 f2 = __half22float2(v[16]);
    float2 f3 = __half22float2(v[17]);
    float2 r  = make_float2((f0.x + f1.x + f2.x + f3.x) * 0.25f,
                            (f0.y + f1.y + f2.y + f3.y) * 0.25f);

    *reinterpret_cast<float2*>(&out[(size_t)node * DCH + 2 * tid]) = r;
}

// ===================== launch ===============================================
extern "C" void kernel_launch(void* const* d_in, const int* in_sizes, int n_in,
                              void* d_out, int out_size)
{
    const float* x    = nullptr;
    const void*  nbrs = nullptr;
    const float* W    = nullptr;

    for (int i = 0; i < n_in; i++) {
        if      (in_sizes[i] == M_NODES * DCH)   x    = (const float*)d_in[i];
        else if (in_sizes[i] == M_NODES * K_NBR) nbrs = d_in[i];
        else if (in_sizes[i] == DCH * DCH)       W    = (const float*)d_in[i];
    }
    if (!x)    x    = (const float*)d_in[0];
    if (!nbrs) nbrs = d_in[1];
    if (!W)    W    = (const float*)d_in[2];

    convert_w<<<(DCH * DCH / 4 + 255) / 256, 256>>>(W);

    dim3 ggrid((M_NODES + 127) / 128, 2);
    gemm_mma<<<ggrid, 256>>>(x);

    gather_trim<<<M_NODES, 128>>>(nbrs, (float*)d_out);
}